// round 1
// baseline (speedup 1.0000x reference)
#include <cuda_runtime.h>

// Problem constants (fixed by the reference: B=32, C=2, H=512, W=512, L=3)
#define BB   32
#define HH   512
#define WW   512
#define LVAL 3.0f

// Per-sample double accumulators (scratch via __device__ global — no allocs allowed)
__device__ double g_part[BB];

__global__ void zero_kernel() {
    int i = threadIdx.x;
    if (i < BB) g_part[i] = 0.0;
}

// Grid: (H, B). Block: 256 threads. Each block handles one (b, y) row.
__global__ __launch_bounds__(256) void symloss_kernel(
    const float* __restrict__ Flow,   // (B,2,H,W)
    const float* __restrict__ Asym,   // (B,2)
    const float* __restrict__ Bsym,   // (B,2)
    const float* __restrict__ Mask)   // (B,2,H,W)
{
    const int y = blockIdx.x;
    const int b = blockIdx.y;

    // Per-sample scalars (cheap; every thread recomputes identically)
    const float a0 = Asym[2 * b];
    const float a1 = Asym[2 * b + 1];
    const float b0 = Bsym[2 * b];
    const float b1 = Bsym[2 * b + 1];

    const float dx  = -LVAL * a0;
    const float dy  = fabsf(LVAL * a1);
    const float dy1 = floorf(dy);
    const float dx1 = floorf(dx);
    const float fy  = dy - dy1;
    const float fx  = dx - dx1;
    const int iy1 = (int)dy1;          // >= 0
    const int ix1 = (int)dx1;          // may be negative

    const int hp   = HH - 1 - iy1;
    const int x_lo = max(0, -ix1);
    const int x_hi = min(WW, WW - 1 - ix1);

    const float w11 = (1.f - fx) * (1.f - fy);
    const float w12 = fx * (1.f - fy);
    const float w21 = (1.f - fx) * fy;
    const float w22 = fx * fy;

    float sum = 0.f;

    if (y < hp && x_hi > x_lo) {
        const int r1 = y + iy1;        // <= H-2 inside valid region
        const int r2 = r1 + 1;         // <= H-1

        const float* f0   = Flow + ((size_t)(b * 2 + 0) * HH) * WW;
        const float* f1   = Flow + ((size_t)(b * 2 + 1) * HH) * WW;
        const float* f0y  = f0 + (size_t)y  * WW;
        const float* f1y  = f1 + (size_t)y  * WW;
        const float* f0r1 = f0 + (size_t)r1 * WW;
        const float* f0r2 = f0 + (size_t)r2 * WW;
        const float* f1r1 = f1 + (size_t)r1 * WW;
        const float* f1r2 = f1 + (size_t)r2 * WW;
        const float* m0   = Mask + ((size_t)(b * 2 + 0) * HH + y) * WW;
        const float* m1   = Mask + ((size_t)(b * 2 + 1) * HH + y) * WW;

        for (int x = x_lo + (int)threadIdx.x; x < x_hi; x += (int)blockDim.x) {
            const int c = x + ix1;     // in [0, W-2] inside valid region
            // channel 0
            const float F11_0 = f0r1[c];
            const float F12_0 = f0r1[c + 1];
            const float F21_0 = f0r2[c];
            const float F22_0 = f0r2[c + 1];
            // channel 1
            const float F11_1 = f1r1[c];
            const float F12_1 = f1r1[c + 1];
            const float F21_1 = f1r2[c];
            const float F22_1 = f1r2[c + 1];

            const float ph0 = w22 * F22_0 + w21 * F21_0 + w12 * F12_0 + w11 * F11_0;
            const float ph1 = w22 * F22_1 + w21 * F21_1 + w12 * F12_1 + w11 * F11_1;

            const float d0 = f0y[x] - ph0;
            const float d1 = f1y[x] - ph1;
            const float s  = d1 * b0 - d0 * b1;

            sum += (m0[x] + m1[x]) * (s * s);
        }
    }

    // Block reduction (warp shuffle + shared)
    __shared__ float warp_sums[8];
    #pragma unroll
    for (int o = 16; o > 0; o >>= 1)
        sum += __shfl_down_sync(0xffffffffu, sum, o);

    const int lane = threadIdx.x & 31;
    const int wid  = threadIdx.x >> 5;
    if (lane == 0) warp_sums[wid] = sum;
    __syncthreads();

    if (wid == 0) {
        sum = (lane < (blockDim.x >> 5)) ? warp_sums[lane] : 0.f;
        #pragma unroll
        for (int o = 4; o > 0; o >>= 1)
            sum += __shfl_down_sync(0xffffffffu, sum, o);
        if (lane == 0 && sum != 0.f) {
            const float denom = 2.f * (float)max(hp, 1) * (float)max(x_hi - x_lo, 1);
            atomicAdd(&g_part[b], (double)(sum / denom) * (1.0 / (double)BB));
        }
    }
}

__global__ void finalize_kernel(float* __restrict__ out) {
    double acc = 0.0;
    #pragma unroll
    for (int i = 0; i < BB; i++) acc += g_part[i];
    out[0] = (float)acc;
}

extern "C" void kernel_launch(void* const* d_in, const int* in_sizes, int n_in,
                              void* d_out, int out_size) {
    const float* Flow = (const float*)d_in[0];
    const float* Asym = (const float*)d_in[1];
    const float* Bsym = (const float*)d_in[2];
    const float* Mask = (const float*)d_in[3];
    float* out = (float*)d_out;

    zero_kernel<<<1, 32>>>();
    dim3 grid(HH, BB);
    symloss_kernel<<<grid, 256>>>(Flow, Asym, Bsym, Mask);
    finalize_kernel<<<1, 1>>>(out);
}

// round 2
// speedup vs baseline: 1.5624x; 1.5624x over previous
#include <cuda_runtime.h>

// Problem constants (fixed by reference: B=32, C=2, H=512, W=512, L=3)
#define BB   32
#define HH   512
#define WW   512
#define LVAL 3.0f
#define NBLOCKS (HH / 2 * BB)

// Persistent scratch (allocation-free). Zero-initialized at module load;
// the last block resets it after each run so graph replays stay correct.
__device__ double g_part[BB];
__device__ unsigned int g_count = 0;

// Select 5 consecutive floats starting at warp-uniform phase o from two
// aligned float4s (A = block k, B = block k+1).
__device__ __forceinline__ void sel5(const float4 A, const float4 B, const int o, float v[5]) {
    switch (o) {
    case 0:  v[0]=A.x; v[1]=A.y; v[2]=A.z; v[3]=A.w; v[4]=B.x; break;
    case 1:  v[0]=A.y; v[1]=A.z; v[2]=A.w; v[3]=B.x; v[4]=B.y; break;
    case 2:  v[0]=A.z; v[1]=A.w; v[2]=B.x; v[3]=B.y; v[4]=B.z; break;
    default: v[0]=A.w; v[1]=B.x; v[2]=B.y; v[3]=B.z; v[4]=B.w; break;
    }
}

// Grid: (H/2, B). Block: 256 threads = 2 sub-rows x 128 chunk-threads.
// Thread (s, j) handles pixels x in [4j, 4j+4) of row y = 2*bx + s.
__global__ __launch_bounds__(256) void symloss_kernel(
    const float* __restrict__ Flow,   // (B,2,H,W)
    const float* __restrict__ Asym,   // (B,2)
    const float* __restrict__ Bsym,   // (B,2)
    const float* __restrict__ Mask,   // (B,2,H,W)
    float* __restrict__ out)
{
    const int b  = blockIdx.y;
    const int s  = threadIdx.x >> 7;
    const int j  = threadIdx.x & 127;
    const int y  = (blockIdx.x << 1) | s;
    const int x0 = j << 2;

    const float a0 = Asym[2 * b];
    const float a1 = Asym[2 * b + 1];
    const float b0 = Bsym[2 * b];
    const float b1 = Bsym[2 * b + 1];

    const float dxs = -LVAL * a0;
    const float dys = fabsf(LVAL * a1);
    const float dy1 = floorf(dys);
    const float dx1 = floorf(dxs);
    const float fy  = dys - dy1;
    const float fx  = dxs - dx1;
    const int iy1 = (int)dy1;          // >= 0
    const int ix1 = (int)dx1;          // may be negative

    const int hp   = HH - 1 - iy1;
    const int x_lo = max(0, -ix1);
    const int x_hi = min(WW, WW - 1 - ix1);

    const float w11 = (1.f - fx) * (1.f - fy);
    const float w12 = fx * (1.f - fy);
    const float w21 = (1.f - fx) * fy;
    const float w22 = fx * fy;

    float sum = 0.f;

    if (y < hp && x_hi > x_lo && x0 + 3 >= x_lo && x0 < x_hi) {
        const int r1 = y + iy1;        // <= H-2 for valid rows
        const int c0 = x0 + ix1;
        const int o  = c0 & 3;         // warp-uniform (x0 % 4 == 0)
        const int a  = c0 - o;         // 4-aligned

        const float* f0 = Flow + ((size_t)(2 * b) * HH) * WW;
        const float* f1 = f0 + (size_t)HH * WW;
        const float* m0 = Mask + ((size_t)(2 * b) * HH + y) * WW;
        const float* m1 = m0 + (size_t)HH * WW;

        const float4 M0 = *(const float4*)(m0 + x0);
        const float4 M1 = *(const float4*)(m1 + x0);
        const float4 P0 = *(const float4*)(f0 + (size_t)y * WW + x0);
        const float4 P1 = *(const float4*)(f1 + (size_t)y * WW + x0);
        const float M0a[4] = {M0.x, M0.y, M0.z, M0.w};
        const float M1a[4] = {M1.x, M1.y, M1.z, M1.w};
        const float P0a[4] = {P0.x, P0.y, P0.z, P0.w};
        const float P1a[4] = {P1.x, P1.y, P1.z, P1.w};

        bool  val[4];
        #pragma unroll
        for (int i = 0; i < 4; i++) {
            const int x = x0 + i;
            val[i] = (x >= x_lo) && (x < x_hi);
        }

        if (a >= 0 && a + 8 <= WW) {
            // Fast path: two aligned float4 loads per shifted row.
            const float* p0r1 = f0 + (size_t)r1 * WW + a;
            const float* p0r2 = p0r1 + WW;
            const float* p1r1 = f1 + (size_t)r1 * WW + a;
            const float* p1r2 = p1r1 + WW;
            const float4 A00 = *(const float4*)(p0r1);
            const float4 B00 = *(const float4*)(p0r1 + 4);
            const float4 A01 = *(const float4*)(p0r2);
            const float4 B01 = *(const float4*)(p0r2 + 4);
            const float4 A10 = *(const float4*)(p1r1);
            const float4 B10 = *(const float4*)(p1r1 + 4);
            const float4 A11 = *(const float4*)(p1r2);
            const float4 B11 = *(const float4*)(p1r2 + 4);

            float v00[5], v01[5], v10[5], v11[5];
            sel5(A00, B00, o, v00);   // ch0, row r1:  flow0[r1][c0 .. c0+4]
            sel5(A01, B01, o, v01);   // ch0, row r2
            sel5(A10, B10, o, v10);   // ch1, row r1
            sel5(A11, B11, o, v11);   // ch1, row r2

            #pragma unroll
            for (int i = 0; i < 4; i++) {
                const float ph0 = w11 * v00[i] + w12 * v00[i + 1]
                                + w21 * v01[i] + w22 * v01[i + 1];
                const float ph1 = w11 * v10[i] + w12 * v10[i + 1]
                                + w21 * v11[i] + w22 * v11[i + 1];
                const float d0 = P0a[i] - ph0;
                const float d1 = P1a[i] - ph1;
                const float sq = d1 * b0 - d0 * b1;
                sum += (val[i] ? (M0a[i] + M1a[i]) : 0.f) * (sq * sq);
            }
        } else {
            // Edge chunk: scalar loads, only for valid pixels (c in [0, W-2]).
            const float* p0r1 = f0 + (size_t)r1 * WW;
            const float* p0r2 = p0r1 + WW;
            const float* p1r1 = f1 + (size_t)r1 * WW;
            const float* p1r2 = p1r1 + WW;
            #pragma unroll
            for (int i = 0; i < 4; i++) {
                if (!val[i]) continue;
                const int c = x0 + i + ix1;
                const float ph0 = w11 * p0r1[c] + w12 * p0r1[c + 1]
                                + w21 * p0r2[c] + w22 * p0r2[c + 1];
                const float ph1 = w11 * p1r1[c] + w12 * p1r1[c + 1]
                                + w21 * p1r2[c] + w22 * p1r2[c + 1];
                const float d0 = P0a[i] - ph0;
                const float d1 = P1a[i] - ph1;
                const float sq = d1 * b0 - d0 * b1;
                sum += (M0a[i] + M1a[i]) * (sq * sq);
            }
        }
    }

    // Block reduction: warp shuffle + shared.
    __shared__ float warp_sums[8];
    __shared__ bool  is_last;
    #pragma unroll
    for (int off = 16; off > 0; off >>= 1)
        sum += __shfl_down_sync(0xffffffffu, sum, off);

    const int lane = threadIdx.x & 31;
    const int wid  = threadIdx.x >> 5;
    if (lane == 0) warp_sums[wid] = sum;
    __syncthreads();

    if (threadIdx.x == 0) {
        float total = 0.f;
        #pragma unroll
        for (int wv = 0; wv < 8; wv++) total += warp_sums[wv];
        if (total != 0.f) {
            const float denom = 2.f * (float)max(hp, 1) * (float)max(x_hi - x_lo, 1);
            atomicAdd(&g_part[b], (double)(total / denom) * (1.0 / (double)BB));
        }
        __threadfence();
        const unsigned int prev = atomicAdd(&g_count, 1u);
        is_last = (prev == (unsigned int)(NBLOCKS - 1));
    }
    __syncthreads();

    // Last block finalizes and resets state for the next graph replay.
    if (is_last && threadIdx.x == 0) {
        double acc = 0.0;
        #pragma unroll
        for (int i = 0; i < BB; i++) {
            acc += g_part[i];
            g_part[i] = 0.0;
        }
        out[0] = (float)acc;
        __threadfence();
        g_count = 0;
    }
}

extern "C" void kernel_launch(void* const* d_in, const int* in_sizes, int n_in,
                              void* d_out, int out_size) {
    const float* Flow = (const float*)d_in[0];
    const float* Asym = (const float*)d_in[1];
    const float* Bsym = (const float*)d_in[2];
    const float* Mask = (const float*)d_in[3];
    float* out = (float*)d_out;

    dim3 grid(HH / 2, BB);
    symloss_kernel<<<grid, 256>>>(Flow, Asym, Bsym, Mask, out);
}

// round 3
// speedup vs baseline: 1.9974x; 1.2784x over previous
#include <cuda_runtime.h>

// Problem constants (fixed by reference: B=32, C=2, H=512, W=512, L=3)
#define BB   32
#define HH   512
#define WW   512
#define LVAL 3.0f
#define ROWS_PER_BLOCK 8
#define NBLOCKS (HH / ROWS_PER_BLOCK * BB)

// Persistent scratch (allocation-free). Zero-initialized at module load;
// the last block resets it after each run so graph replays stay correct.
__device__ double g_part[BB];
__device__ unsigned int g_count = 0;

// Select 5 consecutive floats starting at warp-uniform phase o from two
// aligned float4s (A = block k, B = block k+1).
__device__ __forceinline__ void sel5(const float4 A, const float4 B, const int o, float v[5]) {
    switch (o) {
    case 0:  v[0]=A.x; v[1]=A.y; v[2]=A.z; v[3]=A.w; v[4]=B.x; break;
    case 1:  v[0]=A.y; v[1]=A.z; v[2]=A.w; v[3]=B.x; v[4]=B.y; break;
    case 2:  v[0]=A.z; v[1]=A.w; v[2]=B.x; v[3]=B.y; v[4]=B.z; break;
    default: v[0]=A.w; v[1]=B.x; v[2]=B.y; v[3]=B.z; v[4]=B.w; break;
    }
}

// Grid: (H/8, B). Block: 256 = 2 subrows x 128 chunk-threads.
// Thread (s, j) handles pixels x in [4j, 4j+4) of rows y = 8*bx + s + 2*it, it=0..3.
__global__ __launch_bounds__(256, 4) void symloss_kernel(
    const float* __restrict__ Flow,   // (B,2,H,W)
    const float* __restrict__ Asym,   // (B,2)
    const float* __restrict__ Bsym,   // (B,2)
    const float* __restrict__ Mask,   // (B,2,H,W)
    float* __restrict__ out)
{
    const int b  = blockIdx.y;
    const int s  = threadIdx.x >> 7;
    const int j  = threadIdx.x & 127;
    const int x0 = j << 2;
    const int ybase = blockIdx.x * ROWS_PER_BLOCK + s;

    const float a0 = Asym[2 * b];
    const float a1 = Asym[2 * b + 1];
    const float b0 = Bsym[2 * b];
    const float b1 = Bsym[2 * b + 1];

    const float dxs = -LVAL * a0;
    const float dys = fabsf(LVAL * a1);
    const float dy1 = floorf(dys);
    const float dx1 = floorf(dxs);
    const float fy  = dys - dy1;
    const float fx  = dxs - dx1;
    const int iy1 = (int)dy1;          // >= 0
    const int ix1 = (int)dx1;          // may be negative

    const int hp   = HH - 1 - iy1;
    const int x_lo = max(0, -ix1);
    const int x_hi = min(WW, WW - 1 - ix1);

    const float w11 = (1.f - fx) * (1.f - fy);
    const float w12 = fx * (1.f - fy);
    const float w21 = (1.f - fx) * fy;
    const float w22 = fx * fy;

    // Iteration-invariant chunk geometry.
    const int c0 = x0 + ix1;
    const int o  = c0 & 3;             // warp-uniform (x0 % 4 == 0)
    const int a  = c0 - o;             // 4-aligned
    const bool chunk_live = (x_hi > x_lo) && (x0 + 3 >= x_lo) && (x0 < x_hi);
    const bool fast = chunk_live && (a >= 0) && (a + 8 <= WW);

    float wv[4];                       // 0/1 per-pixel valid weights (iteration-invariant)
    #pragma unroll
    for (int i = 0; i < 4; i++) {
        const int x = x0 + i;
        wv[i] = ((x >= x_lo) && (x < x_hi)) ? 1.f : 0.f;
    }

    const float* f0 = Flow + ((size_t)(2 * b) * HH) * WW;
    const float* f1 = f0 + (size_t)HH * WW;
    const float* m0base = Mask + ((size_t)(2 * b) * HH) * WW;

    float sum = 0.f;

    #pragma unroll 2
    for (int it = 0; it < 4; it++) {
        const int y = ybase + 2 * it;
        if (!chunk_live || y >= hp) continue;

        const int r1 = y + iy1;        // <= H-2 for valid rows
        const float* m0 = m0base + (size_t)y * WW;
        const float* m1 = m0 + (size_t)HH * WW;

        const float4 M0 = *(const float4*)(m0 + x0);
        const float4 M1 = *(const float4*)(m1 + x0);
        const float4 P0 = *(const float4*)(f0 + (size_t)y * WW + x0);
        const float4 P1 = *(const float4*)(f1 + (size_t)y * WW + x0);
        const float M0a[4] = {M0.x, M0.y, M0.z, M0.w};
        const float M1a[4] = {M1.x, M1.y, M1.z, M1.w};
        const float P0a[4] = {P0.x, P0.y, P0.z, P0.w};
        const float P1a[4] = {P1.x, P1.y, P1.z, P1.w};

        if (fast) {
            const float* p0r1 = f0 + (size_t)r1 * WW + a;
            const float* p0r2 = p0r1 + WW;
            const float* p1r1 = f1 + (size_t)r1 * WW + a;
            const float* p1r2 = p1r1 + WW;
            const float4 A00 = *(const float4*)(p0r1);
            const float4 B00 = *(const float4*)(p0r1 + 4);
            const float4 A01 = *(const float4*)(p0r2);
            const float4 B01 = *(const float4*)(p0r2 + 4);
            const float4 A10 = *(const float4*)(p1r1);
            const float4 B10 = *(const float4*)(p1r1 + 4);
            const float4 A11 = *(const float4*)(p1r2);
            const float4 B11 = *(const float4*)(p1r2 + 4);

            float v00[5], v01[5], v10[5], v11[5];
            sel5(A00, B00, o, v00);   // ch0, row r1: flow0[r1][c0 .. c0+4]
            sel5(A01, B01, o, v01);   // ch0, row r2
            sel5(A10, B10, o, v10);   // ch1, row r1
            sel5(A11, B11, o, v11);   // ch1, row r2

            #pragma unroll
            for (int i = 0; i < 4; i++) {
                const float ph0 = w11 * v00[i] + w12 * v00[i + 1]
                                + w21 * v01[i] + w22 * v01[i + 1];
                const float ph1 = w11 * v10[i] + w12 * v10[i + 1]
                                + w21 * v11[i] + w22 * v11[i + 1];
                const float d0 = P0a[i] - ph0;
                const float d1 = P1a[i] - ph1;
                const float sq = d1 * b0 - d0 * b1;
                sum += (M0a[i] + M1a[i]) * wv[i] * (sq * sq);
            }
        } else {
            // Edge chunk: scalar loads, only for valid pixels (c in [0, W-2]).
            const float* p0r1 = f0 + (size_t)r1 * WW;
            const float* p0r2 = p0r1 + WW;
            const float* p1r1 = f1 + (size_t)r1 * WW;
            const float* p1r2 = p1r1 + WW;
            #pragma unroll
            for (int i = 0; i < 4; i++) {
                if (wv[i] == 0.f) continue;
                const int c = x0 + i + ix1;
                const float ph0 = w11 * p0r1[c] + w12 * p0r1[c + 1]
                                + w21 * p0r2[c] + w22 * p0r2[c + 1];
                const float ph1 = w11 * p1r1[c] + w12 * p1r1[c + 1]
                                + w21 * p1r2[c] + w22 * p1r2[c + 1];
                const float d0 = P0a[i] - ph0;
                const float d1 = P1a[i] - ph1;
                const float sq = d1 * b0 - d0 * b1;
                sum += (M0a[i] + M1a[i]) * (sq * sq);
            }
        }
    }

    // Block reduction: warp shuffle + shared.
    __shared__ float warp_sums[8];
    __shared__ bool  is_last;
    #pragma unroll
    for (int off = 16; off > 0; off >>= 1)
        sum += __shfl_down_sync(0xffffffffu, sum, off);

    const int lane = threadIdx.x & 31;
    const int wid  = threadIdx.x >> 5;
    if (lane == 0) warp_sums[wid] = sum;
    __syncthreads();

    if (threadIdx.x == 0) {
        float total = 0.f;
        #pragma unroll
        for (int wv2 = 0; wv2 < 8; wv2++) total += warp_sums[wv2];
        if (total != 0.f) {
            const float denom = 2.f * (float)max(hp, 1) * (float)max(x_hi - x_lo, 1);
            atomicAdd(&g_part[b], (double)(total / denom) * (1.0 / (double)BB));
        }
        __threadfence();
        const unsigned int prev = atomicAdd(&g_count, 1u);
        is_last = (prev == (unsigned int)(NBLOCKS - 1));
    }
    __syncthreads();

    // Last block finalizes and resets state for the next graph replay.
    if (is_last && threadIdx.x == 0) {
        double acc = 0.0;
        #pragma unroll
        for (int i = 0; i < BB; i++) {
            acc += g_part[i];
            g_part[i] = 0.0;
        }
        out[0] = (float)acc;
        __threadfence();
        g_count = 0;
    }
}

extern "C" void kernel_launch(void* const* d_in, const int* in_sizes, int n_in,
                              void* d_out, int out_size) {
    const float* Flow = (const float*)d_in[0];
    const float* Asym = (const float*)d_in[1];
    const float* Bsym = (const float*)d_in[2];
    const float* Mask = (const float*)d_in[3];
    float* out = (float*)d_out;

    dim3 grid(HH / ROWS_PER_BLOCK, BB);
    symloss_kernel<<<grid, 256>>>(Flow, Asym, Bsym, Mask, out);
}